// round 15
// baseline (speedup 1.0000x reference)
#include <cuda_runtime.h>
#include <cstdint>
#include <cstddef>

#define T_N   1024
#define B_N   64
#define V_N   32000
#define H_N   512

#define GC    32                 // col-members per group
#define GB    4                  // independent batch-groups
#define GRID_R (GC * GB)         // 128 CTAs, 1 per SM
#define BPG   16                 // batches per group
#define CPM   16                 // cols per member
#define NTHR  256
#define NSTEP (T_N + 3)

// ---------------- persistent device scratch ----------------
__device__ float    g_embW0[(size_t)V_N * H_N];   // emb @ Wih0^T + bih0 + bhh0
__device__ float    g_h0[2][B_N * H_N];
__device__ float    g_h1[2][B_N * H_N];
__device__ unsigned g_bar[GB][NSTEP];             // per-(group,step) arrival counters

// ---------------- packed-fp32 helpers ----------------
typedef unsigned long long u64;
__device__ __forceinline__ u64 ffma2(u64 a, u64 b, u64 c) {
    u64 d;
    asm("fma.rn.f32x2 %0, %1, %2, %3;" : "=l"(d) : "l"(a), "l"(b), "l"(c));
    return d;
}
__device__ __forceinline__ float unpack_sum(u64 a) {
    float lo, hi;
    asm("mov.b64 {%0, %1}, %2;" : "=f"(lo), "=f"(hi) : "l"(a));
    return lo + hi;
}
__device__ __forceinline__ u64 dup2(float a) {
    u64 d;
    asm("mov.b64 %0, {%1, %1};" : "=l"(d) : "f"(a));
    return d;
}
__device__ __forceinline__ void unpack2(u64 a, float& lo, float& hi) {
    asm("mov.b64 {%0, %1}, %2;" : "=f"(lo), "=f"(hi) : "l"(a));
}

// ---------------- reset: deterministic per launch / graph replay ----------------
__global__ void reset_kernel() {
    int i = blockIdx.x * blockDim.x + threadIdx.x;
    if (i < B_N * H_N) {
        g_h0[0][i] = 0.f; g_h0[1][i] = 0.f;
        g_h1[0][i] = 0.f; g_h1[1][i] = 0.f;
    }
    if (i < GB * NSTEP) {
        int st = i % NSTEP;
        ((unsigned*)g_bar)[i] = (st == 0) ? (unsigned)GC : 0u;  // step-0 pre-passed
    }
}

// ---------------- embW0[v][h] = emb[v]·Wih0[h] + bih0[h] + bhh0[h] (f32x2) ----------------
__global__ __launch_bounds__(256) void embw_kernel(const float* __restrict__ A,
                                                   const float* __restrict__ W,
                                                   const float* __restrict__ bih,
                                                   const float* __restrict__ bhh) {
    __shared__ float As[8][132];
    __shared__ float Ws[8][132];
    const int tid   = threadIdx.x;
    const int hBase = blockIdx.x * 128;
    const int vBase = blockIdx.y * 128;
    const int lRow  = tid >> 1;
    const int lCol  = (tid & 1) * 4;
    const int tx    = tid & 15;
    const int ty    = tid >> 4;

    const float4* Ap = (const float4*)(A + (size_t)(vBase + lRow) * H_N + lCol);
    const float4* Wp = (const float4*)(W + (size_t)(hBase + lRow) * H_N + lCol);

    u64 acc[8][4];
#pragma unroll
    for (int i = 0; i < 8; i++)
#pragma unroll
        for (int j = 0; j < 4; j++) acc[i][j] = 0ull;

    float4 av = Ap[0];
    float4 wv = Wp[0];

    for (int k0 = 0; k0 < 512; k0 += 8) {
        __syncthreads();
        As[lCol + 0][lRow] = av.x; As[lCol + 1][lRow] = av.y;
        As[lCol + 2][lRow] = av.z; As[lCol + 3][lRow] = av.w;
        Ws[lCol + 0][lRow] = wv.x; Ws[lCol + 1][lRow] = wv.y;
        Ws[lCol + 2][lRow] = wv.z; Ws[lCol + 3][lRow] = wv.w;
        __syncthreads();
        if (k0 + 8 < 512) {
            av = Ap[(k0 + 8) >> 2];
            wv = Wp[(k0 + 8) >> 2];
        }
#pragma unroll
        for (int k = 0; k < 8; k++) {
            float a[8];
            *(float4*)&a[0] = *(const float4*)&As[k][ty * 8];
            *(float4*)&a[4] = *(const float4*)&As[k][ty * 8 + 4];
            ulonglong2 wp0 = *(const ulonglong2*)&Ws[k][tx * 8];
            ulonglong2 wp1 = *(const ulonglong2*)&Ws[k][tx * 8 + 4];
            u64 wq[4] = { wp0.x, wp0.y, wp1.x, wp1.y };
#pragma unroll
            for (int i = 0; i < 8; i++) {
                u64 a2 = dup2(a[i]);
#pragma unroll
                for (int j = 0; j < 4; j++) acc[i][j] = ffma2(a2, wq[j], acc[i][j]);
            }
        }
    }

#pragma unroll
    for (int i = 0; i < 8; i++) {
        const int v = vBase + ty * 8 + i;
        float* orow = &g_embW0[(size_t)v * H_N + hBase + tx * 8];
        float o[8];
#pragma unroll
        for (int j = 0; j < 4; j++) {
            float lo, hi;
            unpack2(acc[i][j], lo, hi);
            int h = hBase + tx * 8 + j * 2;
            o[j * 2 + 0] = lo + __ldg(&bih[h + 0]) + __ldg(&bhh[h + 0]);
            o[j * 2 + 1] = hi + __ldg(&bih[h + 1]) + __ldg(&bhh[h + 1]);
        }
        *(float4*)&orow[0] = *(float4*)&o[0];
        *(float4*)&orow[4] = *(float4*)&o[4];
    }
}

// ---------------- persistent recurrence kernel (bulk-stage + mbarrier) ----------------
// SMEM floats: W0[8192] WA[8192] WB[8192] Hs0[8192] Hs1[8192] Rs0[3072] Rs1[3072] b1[16] mb[4]
#define OFF_W0 0
#define OFF_WA 8192
#define OFF_WB 16384
#define OFF_H0 24576
#define OFF_H1 32768
#define OFF_R0 40960
#define OFF_R1 (OFF_R0 + 3072)
#define OFF_B1 (OFF_R1 + 3072)
#define OFF_MB (OFF_B1 + 16)               // 2 mbarriers (8B each), 8B-aligned
#define SMEM_FLOATS (OFF_MB + 4)
#define SMEM_BYTES  (SMEM_FLOATS * 4)      // ~188.5 KB

#define STAGE_BYTES (BPG * H_N * 4)        // 32768 per buffer

__global__ __launch_bounds__(NTHR, 1) void rnn_kernel(const int*   __restrict__ input,
                                                      const float* __restrict__ Whh0,
                                                      const float* __restrict__ Wih1,
                                                      const float* __restrict__ Whh1,
                                                      const float* __restrict__ bih1,
                                                      const float* __restrict__ bhh1,
                                                      float*       __restrict__ out) {
    extern __shared__ float smem[];
    float* W0s = smem + OFF_W0;
    float* WAs = smem + OFF_WA;
    float* WBs = smem + OFF_WB;
    float* Rs0 = smem + OFF_R0;
    float* Rs1 = smem + OFF_R1;
    float* b1s = smem + OFF_B1;

    const int tid  = threadIdx.x;
    const int cid  = blockIdx.x;
    const int m    = cid & (GC - 1);   // member: cols [m*16, m*16+16)
    const int grp  = cid >> 5;         // group: batches [grp*16, grp*16+16)
    const int gb16 = grp * BPG;
    const int w    = tid >> 5;
    const int lane = tid & 31;
    const int o    = w >> 2;           // batch-oct (0..1)
    const int cq   = w & 3;            // col-quad  (0..3)

    const unsigned sd0 = (unsigned)__cvta_generic_to_shared(smem + OFF_H0);
    const unsigned sd1 = (unsigned)__cvta_generic_to_shared(smem + OFF_H1);
    const unsigned mb0 = (unsigned)__cvta_generic_to_shared(smem + OFF_MB);
    const unsigned mb1 = mb0 + 8;

    // ---- preload weight slices: rows [m*16, m*16+16); init mbarriers ----
    {
        const float4* s0 = (const float4*)Whh0 + (size_t)m * 2048;
        const float4* s1 = (const float4*)Wih1 + (size_t)m * 2048;
        const float4* s2 = (const float4*)Whh1 + (size_t)m * 2048;
        float4* d0 = (float4*)W0s; float4* d1 = (float4*)WAs; float4* d2 = (float4*)WBs;
        for (int r = tid; r < 2048; r += NTHR) {
            d0[r] = __ldg(&s0[r]);
            d1[r] = __ldg(&s1[r]);
            d2[r] = __ldg(&s2[r]);
        }
        if (tid < CPM) b1s[tid] = __ldg(&bih1[m * CPM + tid]) + __ldg(&bhh1[m * CPM + tid]);
        if (tid == 0) {
            asm volatile("mbarrier.init.shared.b64 [%0], 1;" :: "r"(mb0) : "memory");
            asm volatile("mbarrier.init.shared.b64 [%0], 1;" :: "r"(mb1) : "memory");
        }
    }
    __syncthreads();

    // read-phase decode: thread tid owns output tid = b*16 + c
    const int b_out  = gb16 + (tid >> 4);
    const int c_glob = m * CPM + (tid & 15);

    const ulonglong2* W0u = (const ulonglong2*)W0s;
    const ulonglong2* WAu = (const ulonglong2*)WAs;
    const ulonglong2* WBu = (const ulonglong2*)WBs;
    const ulonglong2* H0u = (const ulonglong2*)(smem + OFF_H0);
    const ulonglong2* H1u = (const ulonglong2*)(smem + OFF_H1);

    u64 acc0[8][4], accA[8][4];

#define MMA1_BODY(J, W0Q, WAQ)                                                   \
    {                                                                            \
        _Pragma("unroll")                                                        \
        for (int i = 0; i < 8; i++) {                                            \
            ulonglong2 hv = H0u[(o * 8 + i) * 128 + (J) * 32 + lane];            \
            _Pragma("unroll")                                                    \
            for (int c = 0; c < 4; c++) {                                        \
                acc0[i][c] = ffma2(hv.x, W0Q[c].x, acc0[i][c]);                  \
                acc0[i][c] = ffma2(hv.y, W0Q[c].y, acc0[i][c]);                  \
                accA[i][c] = ffma2(hv.x, WAQ[c].x, accA[i][c]);                  \
                accA[i][c] = ffma2(hv.y, WAQ[c].y, accA[i][c]);                  \
            }                                                                    \
        }                                                                        \
    }

#define LOAD_W1(J, W0Q, WAQ)                                                     \
    _Pragma("unroll")                                                            \
    for (int c = 0; c < 4; c++) {                                                \
        int row = cq * 4 + c;                                                    \
        W0Q[c] = W0u[row * 128 + (J) * 32 + lane];                               \
        WAQ[c] = WAu[row * 128 + (J) * 32 + lane];                               \
    }

#define MMA2_BODY(J, WBQ)                                                        \
    {                                                                            \
        _Pragma("unroll")                                                        \
        for (int i = 0; i < 8; i++) {                                            \
            ulonglong2 hv = H1u[(o * 8 + i) * 128 + (J) * 32 + lane];            \
            _Pragma("unroll")                                                    \
            for (int c = 0; c < 4; c++) {                                        \
                accA[i][c] = ffma2(hv.x, WBQ[c].x, accA[i][c]);                  \
                accA[i][c] = ffma2(hv.y, WBQ[c].y, accA[i][c]);                  \
            }                                                                    \
        }                                                                        \
    }

#define LOAD_W2(J, WBQ)                                                          \
    _Pragma("unroll")                                                            \
    for (int c = 0; c < 4; c++)                                                  \
        WBQ[c] = WBu[(cq * 4 + c) * 128 + (J) * 32 + lane];

    // shfl16+shfl8 pre-reduce -> RS rows of 8, stride 12 (float4-aligned, conflict-free)
#define REDUCE8(RS, ACC)                                                         \
    _Pragma("unroll")                                                            \
    for (int i = 0; i < 8; i++)                                                  \
        _Pragma("unroll")                                                        \
        for (int c = 0; c < 4; c++) {                                            \
            float v = unpack_sum(ACC[i][c]);                                     \
            v += __shfl_xor_sync(0xffffffffu, v, 16);                            \
            v += __shfl_xor_sync(0xffffffffu, v, 8);                             \
            if (lane < 8)                                                        \
                (RS)[((o * 8 + i) * 16 + cq * 4 + c) * 12 + lane] = v;           \
        }

    // mbarrier parity wait (acquire)
#define MBAR_WAIT(ADDR, PH)                                                      \
    asm volatile(                                                                \
        "{\n\t"                                                                  \
        ".reg .pred P1;\n\t"                                                     \
        "WAIT_LP_%=:\n\t"                                                        \
        "mbarrier.try_wait.parity.acquire.cta.shared::cta.b64 P1, [%0], %1, 0x989680;\n\t" \
        "@P1 bra.uni WAIT_DN_%=;\n\t"                                            \
        "bra.uni WAIT_LP_%=;\n\t"                                                \
        "WAIT_DN_%=:\n\t"                                                        \
        "}"                                                                      \
        :: "r"(ADDR), "r"((unsigned)(PH)) : "memory");

    for (int s = 1; s <= T_N + 1; s++) {
        const bool doH0 = (s <= T_N);
        const bool doH1 = (s >= 2);
        const unsigned par = (unsigned)((s - 1) & 1);

        // ---- gather input-projection value early (independent) ----
        float xw = 0.f;
        if (doH0) {
            int tok = __ldg(&input[(s - 1) * B_N + b_out]);
            xw = __ldcg(&g_embW0[(size_t)tok * H_N + c_glob]);
        }

        // ---- tid0: poll group counter, then launch both bulk stages ----
        if (tid == 0) {
            const unsigned* bp = &g_bar[grp][s - 1];
            unsigned v;
            do {
                asm volatile("ld.acquire.gpu.global.u32 %0, [%1];"
                             : "=r"(v) : "l"(bp) : "memory");
            } while (v < (unsigned)GC);
            const float* h0src = &g_h0[s & 1][gb16 * H_N];
            const float* h1src = &g_h1[(s + 1) & 1][gb16 * H_N];
            asm volatile("mbarrier.arrive.expect_tx.shared.b64 _, [%0], %1;"
                         :: "r"(mb0), "r"((unsigned)STAGE_BYTES) : "memory");
            asm volatile("cp.async.bulk.shared::cluster.global.mbarrier::complete_tx::bytes "
                         "[%0], [%1], %2, [%3];"
                         :: "r"(sd0), "l"(h0src), "r"((unsigned)STAGE_BYTES), "r"(mb0)
                         : "memory");
            asm volatile("mbarrier.arrive.expect_tx.shared.b64 _, [%0], %1;"
                         :: "r"(mb1), "r"((unsigned)STAGE_BYTES) : "memory");
            asm volatile("cp.async.bulk.shared::cluster.global.mbarrier::complete_tx::bytes "
                         "[%0], [%1], %2, [%3];"
                         :: "r"(sd1), "l"(h1src), "r"((unsigned)STAGE_BYTES), "r"(mb1)
                         : "memory");
        }

#pragma unroll
        for (int i = 0; i < 8; i++)
#pragma unroll
            for (int c = 0; c < 4; c++) { acc0[i][c] = 0ull; accA[i][c] = 0ull; }

        // ---- hoist chunk-0 weights, then wait for h0 (per-warp, no syncthreads) ----
        ulonglong2 w0q[4], waq[4];
        LOAD_W1(0, w0q, waq)
        MBAR_WAIT(mb0, par)

        // ---- pass 1 (fused Whh0 + Wih1 on h0[s-2]) ----
        MMA1_BODY(0, w0q, waq)
        LOAD_W1(1, w0q, waq)
        MMA1_BODY(1, w0q, waq)
        LOAD_W1(2, w0q, waq)
        MMA1_BODY(2, w0q, waq)
        LOAD_W1(3, w0q, waq)
        MMA1_BODY(3, w0q, waq)

        // ---- wait for h1, then pass 2 (Whh1 on h1[s-3]) ----
        ulonglong2 wbq[4];
        LOAD_W2(0, wbq)
        MBAR_WAIT(mb1, par)
        MMA2_BODY(0, wbq)
        LOAD_W2(1, wbq)
        MMA2_BODY(1, wbq)
        LOAD_W2(2, wbq)
        MMA2_BODY(2, wbq)
        LOAD_W2(3, wbq)
        MMA2_BODY(3, wbq)

        // ---- merged reduce (one sync) ----
        REDUCE8(Rs0, acc0)
        REDUCE8(Rs1, accA)
        __syncthreads();

        // ---- epilogues (vectorized reduce read: 2x LDS.128) ----
        if (doH0) {
            const float4* r4 = (const float4*)&Rs0[tid * 12];
            float4 q0 = r4[0], q1 = r4[1];
            float ssum = (q0.x + q0.y) + (q0.z + q0.w) + (q1.x + q1.y) + (q1.z + q1.w);
            __stcg(&g_h0[(s - 1) & 1][b_out * H_N + c_glob], tanhf(ssum + xw));
        }
        if (doH1) {
            const float4* r4 = (const float4*)&Rs1[tid * 12];
            float4 q0 = r4[0], q1 = r4[1];
            float ssum = (q0.x + q0.y) + (q0.z + q0.w) + (q1.x + q1.y) + (q1.z + q1.w);
            float v = tanhf(ssum + b1s[tid & 15]);
            __stcg(&g_h1[s & 1][b_out * H_N + c_glob], v);
            if (s == T_N + 1) __stcg(&out[b_out * H_N + c_glob], v);
        }

        // ---- publish: one release-reduction on the group counter ----
        __syncthreads();
        if (tid == 0)
            asm volatile("red.release.gpu.global.add.u32 [%0], 1;"
                         :: "l"(&g_bar[grp][s]) : "memory");
    }
#undef MMA1_BODY
#undef LOAD_W1
#undef MMA2_BODY
#undef LOAD_W2
#undef REDUCE8
#undef MBAR_WAIT
}

// ---------------- launch ----------------
extern "C" void kernel_launch(void* const* d_in, const int* in_sizes, int n_in,
                              void* d_out, int out_size) {
    const int*   input = (const int*)  d_in[0];
    const float* emb   = (const float*)d_in[1];
    const float* Wih0  = (const float*)d_in[2];
    const float* Whh0  = (const float*)d_in[3];
    const float* bih0  = (const float*)d_in[4];
    const float* bhh0  = (const float*)d_in[5];
    const float* Wih1  = (const float*)d_in[6];
    const float* Whh1  = (const float*)d_in[7];
    const float* bih1  = (const float*)d_in[8];
    const float* bhh1  = (const float*)d_in[9];
    float* out = (float*)d_out;

    cudaFuncSetAttribute(rnn_kernel, cudaFuncAttributeMaxDynamicSharedMemorySize, SMEM_BYTES);

    reset_kernel<<<(B_N * H_N + 255) / 256, 256>>>();
    embw_kernel<<<dim3(H_N / 128, V_N / 128), 256>>>(emb, Wih0, bih0, bhh0);
    rnn_kernel<<<GRID_R, NTHR, SMEM_BYTES>>>(input, Whh0, Wih1, Whh1, bih1, bhh1, out);
}

// round 16
// speedup vs baseline: 1.0076x; 1.0076x over previous
#include <cuda_runtime.h>
#include <cstdint>
#include <cstddef>

#define T_N   1024
#define B_N   64
#define V_N   32000
#define H_N   512

#define GC    32                 // col-members per group
#define GB    4                  // independent batch-groups
#define GRID_R (GC * GB)         // 128 CTAs, 1 per SM
#define BPG   16                 // batches per group
#define CPM   16                 // cols per member
#define NTHR  256
#define NSTEP (T_N + 3)

// ---------------- persistent device scratch ----------------
__device__ float    g_embW0[(size_t)V_N * H_N];   // emb @ Wih0^T + bih0 + bhh0
__device__ float    g_h0[2][B_N * H_N];
__device__ float    g_h1[2][B_N * H_N];
__device__ unsigned g_bar[GB][NSTEP];             // per-(group,step) arrival counters

// ---------------- packed-fp32 helpers ----------------
typedef unsigned long long u64;
__device__ __forceinline__ u64 ffma2(u64 a, u64 b, u64 c) {
    u64 d;
    asm("fma.rn.f32x2 %0, %1, %2, %3;" : "=l"(d) : "l"(a), "l"(b), "l"(c));
    return d;
}
__device__ __forceinline__ float unpack_sum(u64 a) {
    float lo, hi;
    asm("mov.b64 {%0, %1}, %2;" : "=f"(lo), "=f"(hi) : "l"(a));
    return lo + hi;
}
__device__ __forceinline__ u64 dup2(float a) {
    u64 d;
    asm("mov.b64 %0, {%1, %1};" : "=l"(d) : "f"(a));
    return d;
}
__device__ __forceinline__ void unpack2(u64 a, float& lo, float& hi) {
    asm("mov.b64 {%0, %1}, %2;" : "=f"(lo), "=f"(hi) : "l"(a));
}

// ---------------- reset: deterministic per launch / graph replay ----------------
__global__ void reset_kernel() {
    int i = blockIdx.x * blockDim.x + threadIdx.x;
    if (i < B_N * H_N) {
        g_h0[0][i] = 0.f; g_h0[1][i] = 0.f;
        g_h1[0][i] = 0.f; g_h1[1][i] = 0.f;
    }
    if (i < GB * NSTEP) {
        int st = i % NSTEP;
        ((unsigned*)g_bar)[i] = (st == 0) ? (unsigned)GC : 0u;  // step-0 pre-passed
    }
}

// ---------------- embW0[v][h] = emb[v]·Wih0[h] + bih0[h] + bhh0[h] (f32x2) ----------------
__global__ __launch_bounds__(256) void embw_kernel(const float* __restrict__ A,
                                                   const float* __restrict__ W,
                                                   const float* __restrict__ bih,
                                                   const float* __restrict__ bhh) {
    __shared__ float As[8][132];
    __shared__ float Ws[8][132];
    const int tid   = threadIdx.x;
    const int hBase = blockIdx.x * 128;
    const int vBase = blockIdx.y * 128;
    const int lRow  = tid >> 1;
    const int lCol  = (tid & 1) * 4;
    const int tx    = tid & 15;
    const int ty    = tid >> 4;

    const float4* Ap = (const float4*)(A + (size_t)(vBase + lRow) * H_N + lCol);
    const float4* Wp = (const float4*)(W + (size_t)(hBase + lRow) * H_N + lCol);

    u64 acc[8][4];
#pragma unroll
    for (int i = 0; i < 8; i++)
#pragma unroll
        for (int j = 0; j < 4; j++) acc[i][j] = 0ull;

    float4 av = Ap[0];
    float4 wv = Wp[0];

    for (int k0 = 0; k0 < 512; k0 += 8) {
        __syncthreads();
        As[lCol + 0][lRow] = av.x; As[lCol + 1][lRow] = av.y;
        As[lCol + 2][lRow] = av.z; As[lCol + 3][lRow] = av.w;
        Ws[lCol + 0][lRow] = wv.x; Ws[lCol + 1][lRow] = wv.y;
        Ws[lCol + 2][lRow] = wv.z; Ws[lCol + 3][lRow] = wv.w;
        __syncthreads();
        if (k0 + 8 < 512) {
            av = Ap[(k0 + 8) >> 2];
            wv = Wp[(k0 + 8) >> 2];
        }
#pragma unroll
        for (int k = 0; k < 8; k++) {
            float a[8];
            *(float4*)&a[0] = *(const float4*)&As[k][ty * 8];
            *(float4*)&a[4] = *(const float4*)&As[k][ty * 8 + 4];
            ulonglong2 wp0 = *(const ulonglong2*)&Ws[k][tx * 8];
            ulonglong2 wp1 = *(const ulonglong2*)&Ws[k][tx * 8 + 4];
            u64 wq[4] = { wp0.x, wp0.y, wp1.x, wp1.y };
#pragma unroll
            for (int i = 0; i < 8; i++) {
                u64 a2 = dup2(a[i]);
#pragma unroll
                for (int j = 0; j < 4; j++) acc[i][j] = ffma2(a2, wq[j], acc[i][j]);
            }
        }
    }

#pragma unroll
    for (int i = 0; i < 8; i++) {
        const int v = vBase + ty * 8 + i;
        float* orow = &g_embW0[(size_t)v * H_N + hBase + tx * 8];
        float o[8];
#pragma unroll
        for (int j = 0; j < 4; j++) {
            float lo, hi;
            unpack2(acc[i][j], lo, hi);
            int h = hBase + tx * 8 + j * 2;
            o[j * 2 + 0] = lo + __ldg(&bih[h + 0]) + __ldg(&bhh[h + 0]);
            o[j * 2 + 1] = hi + __ldg(&bih[h + 1]) + __ldg(&bhh[h + 1]);
        }
        *(float4*)&orow[0] = *(float4*)&o[0];
        *(float4*)&orow[4] = *(float4*)&o[4];
    }
}

// ---------------- persistent recurrence kernel (R13 staging + lean reduce) ----------------
// SMEM floats: W0[8192] WA[8192] WB[8192] Hs0[8192] Hs1[8192] Rs0[3072] Rs1[3072] b1[16]
#define OFF_W0 0
#define OFF_WA 8192
#define OFF_WB 16384
#define OFF_H0 24576
#define OFF_H1 32768
#define OFF_R0 40960
#define OFF_R1 (OFF_R0 + 3072)
#define OFF_B1 (OFF_R1 + 3072)
#define SMEM_FLOATS (OFF_B1 + 16)
#define SMEM_BYTES  (SMEM_FLOATS * 4)       // ~188.5 KB

__global__ __launch_bounds__(NTHR, 1) void rnn_kernel(const int*   __restrict__ input,
                                                      const float* __restrict__ Whh0,
                                                      const float* __restrict__ Wih1,
                                                      const float* __restrict__ Whh1,
                                                      const float* __restrict__ bih1,
                                                      const float* __restrict__ bhh1,
                                                      float*       __restrict__ out) {
    extern __shared__ float smem[];
    float* W0s = smem + OFF_W0;
    float* WAs = smem + OFF_WA;
    float* WBs = smem + OFF_WB;
    float* Rs0 = smem + OFF_R0;
    float* Rs1 = smem + OFF_R1;
    float* b1s = smem + OFF_B1;

    const int tid  = threadIdx.x;
    const int cid  = blockIdx.x;
    const int m    = cid & (GC - 1);   // member: cols [m*16, m*16+16)
    const int grp  = cid >> 5;         // group: batches [grp*16, grp*16+16)
    const int gb16 = grp * BPG;
    const int w    = tid >> 5;
    const int lane = tid & 31;
    const int o    = w >> 2;           // batch-oct (0..1)
    const int cq   = w & 3;            // col-quad  (0..3)

    // ---- preload weight slices: rows [m*16, m*16+16) ----
    {
        const float4* s0 = (const float4*)Whh0 + (size_t)m * 2048;
        const float4* s1 = (const float4*)Wih1 + (size_t)m * 2048;
        const float4* s2 = (const float4*)Whh1 + (size_t)m * 2048;
        float4* d0 = (float4*)W0s; float4* d1 = (float4*)WAs; float4* d2 = (float4*)WBs;
        for (int r = tid; r < 2048; r += NTHR) {
            d0[r] = __ldg(&s0[r]);
            d1[r] = __ldg(&s1[r]);
            d2[r] = __ldg(&s2[r]);
        }
        if (tid < CPM) b1s[tid] = __ldg(&bih1[m * CPM + tid]) + __ldg(&bhh1[m * CPM + tid]);
    }
    __syncthreads();

    // read-phase decode: thread tid owns output tid = b*16 + c
    const int b_out  = gb16 + (tid >> 4);
    const int c_glob = m * CPM + (tid & 15);

    const ulonglong2* W0u = (const ulonglong2*)W0s;
    const ulonglong2* WAu = (const ulonglong2*)WAs;
    const ulonglong2* WBu = (const ulonglong2*)WBs;
    const ulonglong2* H0u = (const ulonglong2*)(smem + OFF_H0);
    const ulonglong2* H1u = (const ulonglong2*)(smem + OFF_H1);
    const unsigned sd0 = (unsigned)__cvta_generic_to_shared(smem + OFF_H0);
    const unsigned sd1 = (unsigned)__cvta_generic_to_shared(smem + OFF_H1);

    u64 acc0[8][4], accA[8][4];

    // fused pass-1 body on preloaded weights (k-quarter J)
#define MMA1_BODY(J, W0Q, WAQ)                                                   \
    {                                                                            \
        _Pragma("unroll")                                                        \
        for (int i = 0; i < 8; i++) {                                            \
            ulonglong2 hv = H0u[(o * 8 + i) * 128 + (J) * 32 + lane];            \
            _Pragma("unroll")                                                    \
            for (int c = 0; c < 4; c++) {                                        \
                acc0[i][c] = ffma2(hv.x, W0Q[c].x, acc0[i][c]);                  \
                acc0[i][c] = ffma2(hv.y, W0Q[c].y, acc0[i][c]);                  \
                accA[i][c] = ffma2(hv.x, WAQ[c].x, accA[i][c]);                  \
                accA[i][c] = ffma2(hv.y, WAQ[c].y, accA[i][c]);                  \
            }                                                                    \
        }                                                                        \
    }

#define LOAD_W1(J, W0Q, WAQ)                                                     \
    _Pragma("unroll")                                                            \
    for (int c = 0; c < 4; c++) {                                                \
        int row = cq * 4 + c;                                                    \
        W0Q[c] = W0u[row * 128 + (J) * 32 + lane];                               \
        WAQ[c] = WAu[row * 128 + (J) * 32 + lane];                               \
    }

    // pass-2 chunk body
#define MMA2_BODY(J, WBQ)                                                        \
    {                                                                            \
        _Pragma("unroll")                                                        \
        for (int i = 0; i < 8; i++) {                                            \
            ulonglong2 hv = H1u[(o * 8 + i) * 128 + (J) * 32 + lane];            \
            _Pragma("unroll")                                                    \
            for (int c = 0; c < 4; c++) {                                        \
                accA[i][c] = ffma2(hv.x, WBQ[c].x, accA[i][c]);                  \
                accA[i][c] = ffma2(hv.y, WBQ[c].y, accA[i][c]);                  \
            }                                                                    \
        }                                                                        \
    }

#define LOAD_W2(J, WBQ)                                                          \
    _Pragma("unroll")                                                            \
    for (int c = 0; c < 4; c++)                                                  \
        WBQ[c] = WBu[(cq * 4 + c) * 128 + (J) * 32 + lane];

    // shfl16+shfl8 pre-reduce -> RS rows of 8, stride 12 (conflict-free wr/rd)
#define REDUCE8(RS, ACC)                                                         \
    _Pragma("unroll")                                                            \
    for (int i = 0; i < 8; i++)                                                  \
        _Pragma("unroll")                                                        \
        for (int c = 0; c < 4; c++) {                                            \
            float v = unpack_sum(ACC[i][c]);                                     \
            v += __shfl_xor_sync(0xffffffffu, v, 16);                            \
            v += __shfl_xor_sync(0xffffffffu, v, 8);                             \
            if (lane < 8)                                                        \
                (RS)[((o * 8 + i) * 16 + cq * 4 + c) * 12 + lane] = v;           \
        }

    // stage a full 16-row block as ONE commit group
#define STAGE_FULL(SD, SRC)                                                      \
    {                                                                            \
        _Pragma("unroll")                                                        \
        for (int r = 0; r < 8; r++) {                                            \
            int l   = r * NTHR + tid;          /* 0..2047 f4 */                  \
            int b_l = l >> 7;                                                    \
            int c4  = l & 127;                                                   \
            size_t srcf4 = (size_t)(gb16 + b_l) * 128 + c4;                      \
            asm volatile("cp.async.cg.shared.global [%0], [%1], 16;\n"           \
                         :: "r"((SD) + l * 16), "l"((SRC) + srcf4 * 4));         \
        }                                                                        \
        asm volatile("cp.async.commit_group;\n");                                \
    }

    for (int s = 1; s <= T_N + 1; s++) {
        const bool doH0 = (s <= T_N);
        const bool doH1 = (s >= 2);

        // ---- gather input-projection value early (independent) ----
        float xw = 0.f;
        if (doH0) {
            int tok = __ldg(&input[(s - 1) * B_N + b_out]);
            xw = __ldcg(&g_embW0[(size_t)tok * H_N + c_glob]);
        }

        // ---- barrier: single-counter wait (tid 0 polls one address) ----
        if (tid == 0) {
            const unsigned* bp = &g_bar[grp][s - 1];
            unsigned v;
            do {
                asm volatile("ld.acquire.gpu.global.u32 %0, [%1];"
                             : "=r"(v) : "l"(bp) : "memory");
            } while (v < (unsigned)GC);
        }
        __syncthreads();

        // ---- stage h0[s-2] (group 0) and h1[s-3] (group 1) ----
        STAGE_FULL(sd0, g_h0[s & 1])
        STAGE_FULL(sd1, g_h1[(s + 1) & 1])

#pragma unroll
        for (int i = 0; i < 8; i++)
#pragma unroll
            for (int c = 0; c < 4; c++) { acc0[i][c] = 0ull; accA[i][c] = 0ull; }

        // ---- hoist chunk-0 weights into the h0-stage wait bubble ----
        ulonglong2 w0q[4], waq[4];
        LOAD_W1(0, w0q, waq)
        asm volatile("cp.async.wait_group 1;\n" ::: "memory");
        __syncthreads();

        // ---- pass 1 (fused Whh0 + Wih1 on h0[s-2]) ----
        MMA1_BODY(0, w0q, waq)
        LOAD_W1(1, w0q, waq)
        MMA1_BODY(1, w0q, waq)
        LOAD_W1(2, w0q, waq)
        MMA1_BODY(2, w0q, waq)
        LOAD_W1(3, w0q, waq)
        MMA1_BODY(3, w0q, waq)

        // ---- hoist pass-2 chunk-0 weights into the h1-stage wait bubble ----
        ulonglong2 wbq[4];
        LOAD_W2(0, wbq)
        asm volatile("cp.async.wait_group 0;\n" ::: "memory");
        __syncthreads();

        // ---- pass 2 (Whh1 on h1[s-3]) ----
        MMA2_BODY(0, wbq)
        LOAD_W2(1, wbq)
        MMA2_BODY(1, wbq)
        LOAD_W2(2, wbq)
        MMA2_BODY(2, wbq)
        LOAD_W2(3, wbq)
        MMA2_BODY(3, wbq)

        // ---- merged reduce (one sync for both) ----
        REDUCE8(Rs0, acc0)
        REDUCE8(Rs1, accA)
        __syncthreads();

        // ---- epilogues (vectorized reduce read: 2x LDS.128) ----
        if (doH0) {
            const float4* r4 = (const float4*)&Rs0[tid * 12];
            float4 q0 = r4[0], q1 = r4[1];
            float ssum = (q0.x + q0.y) + (q0.z + q0.w) + (q1.x + q1.y) + (q1.z + q1.w);
            __stcg(&g_h0[(s - 1) & 1][b_out * H_N + c_glob], tanhf(ssum + xw));
        }
        if (doH1) {
            const float4* r4 = (const float4*)&Rs1[tid * 12];
            float4 q0 = r4[0], q1 = r4[1];
            float ssum = (q0.x + q0.y) + (q0.z + q0.w) + (q1.x + q1.y) + (q1.z + q1.w);
            float v = tanhf(ssum + b1s[tid & 15]);
            __stcg(&g_h1[s & 1][b_out * H_N + c_glob], v);
            if (s == T_N + 1) __stcg(&out[b_out * H_N + c_glob], v);
        }

        // ---- publish: one release-reduction on the group counter ----
        __syncthreads();
        if (tid == 0)
            asm volatile("red.release.gpu.global.add.u32 [%0], 1;"
                         :: "l"(&g_bar[grp][s]) : "memory");
    }
#undef MMA1_BODY
#undef LOAD_W1
#undef MMA2_BODY
#undef LOAD_W2
#undef REDUCE8
#undef STAGE_FULL
}

// ---------------- launch ----------------
extern "C" void kernel_launch(void* const* d_in, const int* in_sizes, int n_in,
                              void* d_out, int out_size) {
    const int*   input = (const int*)  d_in[0];
    const float* emb   = (const float*)d_in[1];
    const float* Wih0  = (const float*)d_in[2];
    const float* Whh0  = (const float*)d_in[3];
    const float* bih0  = (const float*)d_in[4];
    const float* bhh0  = (const float*)d_in[5];
    const float* Wih1  = (const float*)d_in[6];
    const float* Whh1  = (const float*)d_in[7];
    const float* bih1  = (const float*)d_in[8];
    const float* bhh1  = (const float*)d_in[9];
    float* out = (float*)d_out;

    cudaFuncSetAttribute(rnn_kernel, cudaFuncAttributeMaxDynamicSharedMemorySize, SMEM_BYTES);

    reset_kernel<<<(B_N * H_N + 255) / 256, 256>>>();
    embw_kernel<<<dim3(H_N / 128, V_N / 128), 256>>>(emb, Wih0, bih0, bhh0);
    rnn_kernel<<<GRID_R, NTHR, SMEM_BYTES>>>(input, Whh0, Wih1, Whh1, bih1, bhh1, out);
}